// round 10
// baseline (speedup 1.0000x reference)
#include <cuda_runtime.h>
#include <cuda_fp16.h>
#include <cstdint>

// ---------------------------------------------------------------------------
// Problem constants
// ---------------------------------------------------------------------------
#define S_   7
#define BATCH 8192
#define D_   1024
#define E_   256
#define H_   512
#define SH_  256
#define V_   100
#define D0_  1280
#define H4_  2048

typedef __half half_t;

#define H1K  1024   // h1 split hi/lo (side chain)
#define HIDK 512    // hidden split hi/lo (side chain)
#define NP   3072   // combined precompute N: [gates0 2048 | gateN 512 | lin 512]

// ---------------------------------------------------------------------------
// Device scratch
// ---------------------------------------------------------------------------
__device__ float g_P    [S_ * BATCH * NP];       // cols 0-2047 gates0 partial (gate-ilv,
                                                 // bias folded); 2048-2559 gateN(+bias);
                                                 // 2560-3071 lin (full)
__device__ half_t g_Apre [S_ * BATCH * D0_];     // [inputs | emb_s]
__device__ half_t g_WPre [S_ * NP * D0_];        // [W_ih0 full (ilv) | hwN[:, :D0] | hwL full]
__device__ half_t g_Whh0i[S_ * H4_ * H_];        // W_hh0 gate-interleaved
__device__ half_t g_WhhN [S_ * H_ * H_];         // hwN[:, D0:]
__device__ half_t g_Wcat1[S_ * H4_ * 1024];      // [W_ih1 | W_hh1] gate-interleaved
__device__ half_t g_SHW  [S_ * SH_ * H1K];       // [Wh | Wh] dup (A split)
__device__ half_t g_PW   [S_ * V_ * HIDK];       // [Wh | Wh] dup
__device__ half_t g_h0A  [(S_ + 1) * BATCH * H_];
__device__ half_t g_cat1 [(S_ + 1) * BATCH * 1024];
__device__ half_t g_h1p  [S_ * BATCH * H1K];
__device__ half_t g_hid  [S_ * BATCH * HIDK];
__device__ float g_h0f[BATCH * H_], g_c0[BATCH * H_], g_c1[BATCH * H_];
__device__ float g_biasP[S_ * NP], g_bias1[S_ * H4_];

// ---------------------------------------------------------------------------
// PTX helpers
// ---------------------------------------------------------------------------
__device__ __forceinline__ uint32_t smem_u32(const void* p) {
    uint32_t a;
    asm("{ .reg .u64 t; cvta.to.shared.u64 t, %1; cvt.u32.u64 %0, t; }" : "=r"(a) : "l"(p));
    return a;
}
__device__ __forceinline__ uint32_t sw128(uint32_t off) { return off ^ ((off >> 3) & 0x70); }
__device__ __forceinline__ void cpa16(uint32_t dst, const void* src, int sz) {
    asm volatile("cp.async.cg.shared.global [%0], [%1], 16, %2;"
                 :: "r"(dst), "l"(src), "r"(sz) : "memory");
}
__device__ __forceinline__ void ldsm4(uint32_t* r, uint32_t addr) {
    asm volatile("ldmatrix.sync.aligned.m8n8.x4.shared.b16 {%0,%1,%2,%3}, [%4];"
                 : "=r"(r[0]), "=r"(r[1]), "=r"(r[2]), "=r"(r[3]) : "r"(addr));
}
#define MMA_F16(cc, a0, a1, a2, a3, b0, b1)                                    \
    asm volatile("mma.sync.aligned.m16n8k16.row.col.f32.f16.f16.f32 "          \
                 "{%0,%1,%2,%3}, {%4,%5,%6,%7}, {%8,%9}, {%0,%1,%2,%3};\n"     \
                 : "+f"(cc[0]), "+f"(cc[1]), "+f"(cc[2]), "+f"(cc[3])          \
                 : "r"(a0), "r"(a1), "r"(a2), "r"(a3), "r"(b0), "r"(b1))

__device__ __forceinline__ float sigm(float x) { return 1.f / (1.f + __expf(-x)); }

// ---------------------------------------------------------------------------
// Packer. second: -1 plain, 0 dup-hi at +off2, 1 residual-lo at +off2.
// gateH > 0: gate-interleave remap (r -> (r/(4g))*dDrps + 4*(r%g') + gate),
//            dDrps = dst rows per slot.
// else: srcRow=(r/rps)*sDrps+sDro+(r%rps); dstRow=(r/rps)*dDrps+dDro+(r%rps)
// ---------------------------------------------------------------------------
__global__ void conv_pack(const float* __restrict__ src, long srcLd, long srcColOff,
                          long sDrps, long sDro,
                          half_t* __restrict__ dst, long dstLd, long dstColOff,
                          long dDrps, long dDro,
                          int off2, int second, int gateH,
                          long rows, int cols, long rps)
{
    int c4n = cols >> 2;
    long total = rows * c4n;
    long stride = (long)gridDim.x * blockDim.x;
    for (long t = blockIdx.x * (long)blockDim.x + threadIdx.x; t < total; t += stride) {
        long r = t / c4n;
        int  cI = (int)(t - r * c4n) << 2;
        long srow, drow;
        if (gateH > 0) {
            long u = 4L * gateH;
            long q = r / u, n = r - q * u;
            long g = n / gateH, j = n - g * gateH;
            srow = r;
            drow = q * dDrps + 4 * j + g;
        } else {
            long rq = r / rps, rr = r - rq * rps;
            srow = rq * sDrps + sDro + rr;
            drow = rq * dDrps + dDro + rr;
        }
        float4 v = *reinterpret_cast<const float4*>(src + srow * srcLd + srcColOff + cI);
        half_t h0 = __float2half(v.x), h1 = __float2half(v.y);
        half_t h2 = __float2half(v.z), h3 = __float2half(v.w);
        long base = drow * dstLd + dstColOff + cI;
        __half2* p = (__half2*)(dst + base);
        p[0] = __halves2half2(h0, h1);
        p[1] = __halves2half2(h2, h3);
        if (second >= 0) {
            __half2* q2 = (__half2*)(dst + base + off2);
            if (second == 1) {
                half_t l0 = __float2half(v.x - __half2float(h0));
                half_t l1 = __float2half(v.y - __half2float(h1));
                half_t l2 = __float2half(v.z - __half2float(h2));
                half_t l3 = __float2half(v.w - __half2float(h3));
                q2[0] = __halves2half2(l0, l1);
                q2[1] = __halves2half2(l2, l3);
            } else {
                q2[0] = __halves2half2(h0, h1);
                q2[1] = __halves2half2(h2, h3);
            }
        }
    }
}

// Apre[s] = [inputs | emb_s]  (fp16)
__global__ void apre_build(const float* __restrict__ inputs,
                           const float* __restrict__ start,
                           const float* __restrict__ emb,
                           const int* __restrict__ labels)
{
    const long total = (long)S_ * BATCH * (D0_ / 4);
    long stride = (long)gridDim.x * blockDim.x;
    for (long t = blockIdx.x * (long)blockDim.x + threadIdx.x; t < total; t += stride) {
        int c4 = (int)(t % (D0_ / 4));
        long sb = t / (D0_ / 4);
        int b = (int)(sb % BATCH);
        int s = (int)(sb / BATCH);
        int c = c4 * 4;
        float4 v;
        if (c < D_) {
            v = *reinterpret_cast<const float4*>(inputs + (long)b * D_ + c);
        } else {
            int e = c - D_;
            if (s == 0) v = *reinterpret_cast<const float4*>(start + e);
            else {
                int lab = labels[(s - 1) * BATCH + b];
                v = *reinterpret_cast<const float4*>(emb + ((long)(s - 1) * V_ + lab) * E_ + e);
            }
        }
        __half2* p = (__half2*)(g_Apre + ((long)s * BATCH + b) * D0_ + c);
        p[0] = __halves2half2(__float2half(v.x), __float2half(v.y));
        p[1] = __halves2half2(__float2half(v.z), __float2half(v.w));
    }
}

__global__ void misc_init(const float* __restrict__ b_ih0, const float* __restrict__ b_hh0,
                          const float* __restrict__ b_ih1, const float* __restrict__ b_hh1,
                          const float* __restrict__ hwN_b0)
{
    long stride = (long)gridDim.x * blockDim.x;
    long i0 = blockIdx.x * (long)blockDim.x + threadIdx.x;
    for (long t = i0; t < S_ * NP; t += stride) {
        long s = t / NP, n = t % NP;
        float v;
        if (n < 2048) {
            long j = n >> 2, g = n & 3;
            long src = s * H4_ + g * H_ + j;
            v = b_ih0[src] + b_hh0[src];
        } else if (n < 2560) {
            v = hwN_b0[s * H_ + (n - 2048)];
        } else {
            v = 0.f;
        }
        g_biasP[t] = v;
    }
    for (long t = i0; t < S_ * H4_; t += stride) {
        long s = t / H4_, n = t % H4_;
        long j = n >> 2, g = n & 3;
        long src = s * H4_ + g * H_ + j;
        g_bias1[t] = b_ih1[src] + b_hh1[src];
    }
}

// ---------------------------------------------------------------------------
// fp16 NT GEMM, 128x128x64 CTA tile, 8 warps (64x32 warp tiles), 3 stages.
// modes: 0 fp32 C; 1 packed split fp16 (hid); 2 LSTM0; 3 HWY (frag-direct);
//        4 LSTM1.
// ---------------------------------------------------------------------------
#define BM 128
#define BN 128
#define BK 64
#define STG_BYTES 16384
#define SMEM_GEMM (6 * STG_BYTES)

__global__ __launch_bounds__(256, 2)
void gemm_mma(const half_t* __restrict__ A, int lda, long sA,
              const half_t* __restrict__ B, int ldb, long sB,
              float* __restrict__ C, int ldc, long sC,
              const float* __restrict__ Cin, long sCin,
              const float* __restrict__ bias, long sBias,
              half_t* __restrict__ O1, half_t* __restrict__ O2,
              float* __restrict__ X1, float* __restrict__ X2,
              int M, int N, int K, int mode, int relu)
{
    extern __shared__ char smem[];
    const uint32_t sbA = smem_u32(smem);
    const uint32_t sbB = sbA + 3 * STG_BYTES;

    const int z = blockIdx.z;
    A += z * sA;  B += z * sB;
    if (C)    C    += z * sC;
    if (Cin)  Cin  += z * sCin;
    if (bias) bias += z * sBias;

    const int tid = threadIdx.x;
    const int warp = tid >> 5, lane = tid & 31;
    const int m0 = blockIdx.y * BM, n0 = blockIdx.x * BN;
    const int wm = (warp & 1) * 64, wn = (warp >> 1) * 32;

    float c[4][4][4];
#pragma unroll
    for (int i = 0; i < 4; ++i)
#pragma unroll
        for (int j = 0; j < 4; ++j)
#pragma unroll
            for (int r = 0; r < 4; ++r) c[i][j][r] = 0.f;

    const int kT = K / BK;

    auto issue = [&](int t) {
        const int kk = t * BK;
        const uint32_t aBuf = sbA + (t % 3) * STG_BYTES;
        const uint32_t bBuf = sbB + (t % 3) * STG_BYTES;
#pragma unroll
        for (int w = 0; w < 4; ++w) {
            int g = tid + w * 256;
            int row = g >> 3, q = g & 7;
            const char* srcA = (const char*)(A + (long)(m0 + row) * lda + kk) + q * 16;
            cpa16(aBuf + sw128(row * 128 + q * 16), srcA, 16);
        }
#pragma unroll
        for (int w = 0; w < 4; ++w) {
            int g = tid + w * 256;
            int row = g >> 3, q = g & 7;
            int n = n0 + row;
            const char* srcB = (const char*)(B + (long)n * ldb + kk) + q * 16;
            cpa16(bBuf + sw128(row * 128 + q * 16), (n < N) ? srcB : (const char*)B,
                  (n < N) ? 16 : 0);
        }
        asm volatile("cp.async.commit_group;" ::: "memory");
    };

    issue(0);
    if (kT > 1) issue(1);

    for (int t = 0; t < kT; ++t) {
        if (t + 1 < kT) asm volatile("cp.async.wait_group 1;" ::: "memory");
        else            asm volatile("cp.async.wait_group 0;" ::: "memory");
        __syncthreads();
        if (t + 2 < kT) issue(t + 2);

        const uint32_t aS = sbA + (t % 3) * STG_BYTES;
        const uint32_t bS = sbB + (t % 3) * STG_BYTES;
#pragma unroll
        for (int ks = 0; ks < 4; ++ks) {
            uint32_t a[4][4], b[2][4];
            const int colByte = (ks * 16 + ((lane >> 4) << 3)) * 2;
#pragma unroll
            for (int i = 0; i < 4; ++i)
                ldsm4(a[i], aS + sw128((wm + i * 16 + (lane & 15)) * 128 + colByte));
#pragma unroll
            for (int jb = 0; jb < 2; ++jb)
                ldsm4(b[jb], bS + sw128((wn + jb * 16 + (lane & 15)) * 128 + colByte));
#pragma unroll
            for (int i = 0; i < 4; ++i)
#pragma unroll
                for (int j = 0; j < 4; ++j) {
                    const int jb = j >> 1, sel = j & 1;
                    MMA_F16(c[i][j], a[i][0], a[i][1], a[i][2], a[i][3],
                            b[jb][sel], b[jb][sel + 2]);
                }
        }
    }

    if (mode != 2 && mode != 4) {
        // fragment-direct epilogues: 0 (fp32 C), 1 (split hid), 3 (highway)
#pragma unroll
        for (int i = 0; i < 4; ++i) {
#pragma unroll
            for (int rr = 0; rr < 2; ++rr) {
                const int m = m0 + wm + i * 16 + (lane >> 2) + rr * 8;
#pragma unroll
                for (int j = 0; j < 4; ++j) {
                    const int n = n0 + wn + j * 8 + (lane & 3) * 2;
                    if (n < N) {
                        float v0 = c[i][j][rr * 2 + 0];
                        float v1 = c[i][j][rr * 2 + 1];
                        if (mode == 3) {
                            // gateN partial at Cin[.., n]; lin (full) at +512
                            const long ci = (long)m * ldc + n;
                            const float g0 = sigm(v0 + Cin[ci]);
                            const float g1 = sigm(v1 + Cin[ci + 1]);
                            const float l0 = Cin[ci + 512];
                            const float l1 = Cin[ci + 513];
                            const long hx = (long)m * H_ + n;
                            const float cur0 = g0 * X1[hx]     + (1.f - g0) * l0;
                            const float cur1 = g1 * X1[hx + 1] + (1.f - g1) * l1;
                            *(__half2*)(O1 + (long)m * 1024 + n) =
                                __halves2half2(__float2half(cur0), __float2half(cur1));
                        } else {
                            if (bias) { v0 += bias[n]; v1 += bias[n + 1]; }
                            const long idx = (long)m * ldc + n;
                            if (Cin) { v0 += Cin[idx]; v1 += Cin[idx + 1]; }
                            if (relu) { v0 = fmaxf(v0, 0.f); v1 = fmaxf(v1, 0.f); }
                            if (mode == 1) {
                                const long o = (long)m * HIDK + n;
                                half_t h0 = __float2half(v0), h1 = __float2half(v1);
                                half_t l0 = __float2half(v0 - __half2float(h0));
                                half_t l1 = __float2half(v1 - __half2float(h1));
                                *(__half2*)(O1 + o)       = __halves2half2(h0, h1);
                                *(__half2*)(O1 + o + 256) = __halves2half2(l0, l1);
                            } else {
                                float2 st; st.x = v0; st.y = v1;
                                *(float2*)(C + idx) = st;
                            }
                        }
                    }
                }
            }
        }
    } else {
        // LSTM epilogues via smem staging (gate-interleaved N)
        __syncthreads();
        float* sAcc = (float*)smem;
#pragma unroll
        for (int i = 0; i < 4; ++i)
#pragma unroll
            for (int j = 0; j < 4; ++j)
#pragma unroll
                for (int rr = 0; rr < 2; ++rr)
#pragma unroll
                    for (int cc = 0; cc < 2; ++cc)
                        sAcc[(wm + i * 16 + (lane >> 2) + rr * 8) * 132 +
                             wn + j * 8 + (lane & 3) * 2 + cc] = c[i][j][rr * 2 + cc];
        __syncthreads();

        const int jbase = n0 >> 2;
        for (int t2 = tid; t2 < 128 * 32; t2 += 256) {
            const int row = t2 >> 5, jj = t2 & 31;
            const int b = m0 + row, j = jbase + jj;
            float gv[4];
#pragma unroll
            for (int g = 0; g < 4; ++g) {
                float x = sAcc[row * 132 + 4 * jj + g];
                if (mode == 2) x += Cin[(long)b * ldc + n0 + 4 * jj + g];
                else           x += bias[n0 + 4 * jj + g];
                gv[g] = x;
            }
            const float ig = sigm(gv[0]), fg = sigm(gv[1]);
            const float gg = tanhf(gv[2]), og = sigm(gv[3]);
            const long sidx = (long)b * H_ + j;
            const float cn = fg * X1[sidx] + ig * gg;
            const float hn = og * tanhf(cn);
            X1[sidx] = cn;
            half_t hh = __float2half(hn);
            if (mode == 2) {
                X2[sidx] = hn;                       // h0 fp32 for highway
                O1[(long)b * H_ + j] = hh;           // h0A[s+1]
            } else {
                O1[(long)b * 1024 + 512 + j] = hh;   // cat1[s+1] h1 cols
                half_t hl = __float2half(hn - __half2float(hh));
                const long o2 = (long)b * H1K + j;
                O2[o2] = hh; O2[o2 + 512] = hl;      // h1p[s] split
            }
        }
    }
}

// ---------------------------------------------------------------------------
// Host
// ---------------------------------------------------------------------------
#define SYM(var, sym) cudaGetSymbolAddress((void**)&var, sym)

static inline void G(const half_t* A, int lda, long sA,
                     const half_t* B, int ldb, long sB,
                     float* C, int ldc, long sC,
                     const float* Cin, long sCin,
                     const float* bias, long sBias,
                     half_t* O1, half_t* O2, float* X1, float* X2,
                     int M, int N, int K, int mode, int relu, int Z,
                     cudaStream_t st)
{
    dim3 grid((N + BN - 1) / BN, M / BM, Z);
    gemm_mma<<<grid, 256, SMEM_GEMM, st>>>(A, lda, sA, B, ldb, sB, C, ldc, sC,
                                           Cin, sCin, bias, sBias, O1, O2, X1, X2,
                                           M, N, K, mode, relu);
}

extern "C" void kernel_launch(void* const* d_in, const int* in_sizes, int n_in,
                              void* d_out, int out_size)
{
    const float* inputs = (const float*)d_in[0];
    const int*   labels = (const int*)  d_in[1];
    const float* start  = (const float*)d_in[2];
    const float* emb    = (const float*)d_in[3];
    const float* W_ih0  = (const float*)d_in[4];
    const float* W_hh0  = (const float*)d_in[5];
    const float* b_ih0  = (const float*)d_in[6];
    const float* b_hh0  = (const float*)d_in[7];
    const float* hwN_W0 = (const float*)d_in[8];
    const float* hwN_b0 = (const float*)d_in[9];
    const float* hwL_W0 = (const float*)d_in[10];
    const float* W_ih1  = (const float*)d_in[11];
    const float* W_hh1  = (const float*)d_in[12];
    const float* b_ih1  = (const float*)d_in[13];
    const float* b_hh1  = (const float*)d_in[14];
    // d_in[15..17] dead in reference (layer-1 highway output unused)
    const float* sh_W   = (const float*)d_in[18];
    const float* sh_b   = (const float*)d_in[19];
    const float* pred_W = (const float*)d_in[20];
    const float* pred_b = (const float*)d_in[21];
    float* out = (float*)d_out;

    static cudaStream_t sPre = nullptr, sCls = nullptr;
    static cudaEvent_t evA, evP[S_], evM[S_], evLast;
    if (!sPre) {
        int lo, hi;
        cudaDeviceGetStreamPriorityRange(&lo, &hi);   // lo = lowest priority
        cudaStreamCreateWithPriority(&sPre, cudaStreamNonBlocking, lo);
        cudaStreamCreateWithPriority(&sCls, cudaStreamNonBlocking, lo);
        cudaEventCreateWithFlags(&evA, cudaEventDisableTiming);
        cudaEventCreateWithFlags(&evLast, cudaEventDisableTiming);
        for (int i = 0; i < S_; ++i) {
            cudaEventCreateWithFlags(&evP[i], cudaEventDisableTiming);
            cudaEventCreateWithFlags(&evM[i], cudaEventDisableTiming);
        }
        cudaFuncSetAttribute(gemm_mma, cudaFuncAttributeMaxDynamicSharedMemorySize,
                             SMEM_GEMM);
    }

    float *P, *biasP, *bias1, *h0f, *c0, *c1;
    half_t *Apre, *WPre, *Whh0i, *WhhN, *Wcat1, *SHW, *PW;
    half_t *h0A, *cat1, *h1p, *hid;
    SYM(P, g_P); SYM(biasP, g_biasP); SYM(bias1, g_bias1);
    SYM(h0f, g_h0f); SYM(c0, g_c0); SYM(c1, g_c1);
    SYM(Apre, g_Apre); SYM(WPre, g_WPre);
    SYM(Whh0i, g_Whh0i); SYM(WhhN, g_WhhN); SYM(Wcat1, g_Wcat1);
    SYM(SHW, g_SHW); SYM(PW, g_PW);
    SYM(h0A, g_h0A); SYM(cat1, g_cat1); SYM(h1p, g_h1p); SYM(hid, g_hid);

    const long h0sz = (long)BATCH * H_;
    const long c1sz = (long)BATCH * 1024;
    const int CB = 2048;
    const long BIGR = 1L << 40;

    // ---- stream 0: state init + precompute-facing packs ----
    cudaMemsetAsync(c0, 0, h0sz * 4);
    cudaMemsetAsync(c1, 0, h0sz * 4);
    cudaMemsetAsync(h0A, 0, h0sz * 2);    // slot-0 h0
    cudaMemsetAsync(cat1, 0, c1sz * 2);   // slot-0 [cur|h1]
    // WPre rows 0-2047: W_ih0 full, gate-interleaved (dst slot stride NP)
    conv_pack<<<CB, 256>>>(W_ih0, D0_, 0, 0, 0, WPre, D0_, 0, NP, 0,
                           0, -1, H_, (long)S_ * H4_, D0_, BIGR);
    // WPre rows 2048-2559: hwN[:, :D0]
    conv_pack<<<CB, 256>>>(hwN_W0, D0_ + H_, 0, H_, 0, WPre, D0_, 0, NP, 2048,
                           0, -1, 0, (long)S_ * H_, D0_, H_);
    // WPre rows 2560-3071: hwL full
    conv_pack<<<CB, 256>>>(hwL_W0, D0_, 0, H_, 0, WPre, D0_, 0, NP, 2560,
                           0, -1, 0, (long)S_ * H_, D0_, H_);
    apre_build<<<CB, 256>>>(inputs, start, emb, labels);
    misc_init<<<CB, 256>>>(b_ih0, b_hh0, b_ih1, b_hh1, hwN_b0);
    cudaEventRecord(evA, 0);

    // ---- sPre: serial-chain weight packs, then per-slot precompute ----
    conv_pack<<<CB, 256, 0, sPre>>>(W_hh0, H_, 0, 0, 0, Whh0i, H_, 0, H4_, 0,
                                    0, -1, H_, (long)S_ * H4_, H_, BIGR);
    conv_pack<<<CB, 256, 0, sPre>>>(W_ih1, H_, 0, 0, 0, Wcat1, 1024, 0, H4_, 0,
                                    0, -1, H_, (long)S_ * H4_, H_, BIGR);
    conv_pack<<<CB, 256, 0, sPre>>>(W_hh1, H_, 0, 0, 0, Wcat1, 1024, 512, H4_, 0,
                                    0, -1, H_, (long)S_ * H4_, H_, BIGR);
    conv_pack<<<CB, 256, 0, sPre>>>(hwN_W0, D0_ + H_, D0_, 0, 0, WhhN, H_, 0, 0, 0,
                                    0, -1, 0, (long)S_ * H_, H_, BIGR);
    cudaStreamWaitEvent(sPre, evA, 0);
    for (int s = 0; s < S_; ++s) {
        // P[s] = Apre[s] @ WPre[s].T + biasP[s]   (N = 3072, one GEMM)
        G(Apre + (long)s * BATCH * D0_, D0_, 0,
          WPre + (long)s * NP * D0_, D0_, 0,
          P + (long)s * BATCH * NP, NP, 0, nullptr, 0,
          biasP + (long)s * NP, 0,
          nullptr, nullptr, nullptr, nullptr, BATCH, NP, D0_, 0, 0, 1, sPre);
        cudaEventRecord(evP[s], sPre);
    }

    // ---- sCls: classifier weight packs (classifier GEMMs follow in-order) ----
    conv_pack<<<CB, 256, 0, sCls>>>(sh_W, H_, 0, 0, 0, SHW, H1K, 0, 0, 0,
                                    512, 0, 0, (long)S_ * SH_, H_, BIGR);
    conv_pack<<<CB, 256, 0, sCls>>>(pred_W, SH_, 0, 0, 0, PW, HIDK, 0, 0, 0,
                                    256, 0, 0, (long)S_ * V_, SH_, BIGR);

    // ---- serial chain on main stream ----
    for (int s = 0; s < S_; ++s) {
        cudaStreamWaitEvent(0, evP[s], 0);

        // gates0 + LSTM0: h0(s-1) @ W_hh0 + P[s][:, 0:2048]  -> h0(s)
        G(h0A + (long)s * h0sz, H_, 0,
          Whh0i + (long)s * H4_ * H_, H_, 0,
          nullptr, NP, 0, P + (long)s * BATCH * NP, 0, nullptr, 0,
          h0A + (long)(s + 1) * h0sz, nullptr, c0, h0f,
          BATCH, H4_, H_, 2, 0, 1, 0);

        // gateN + highway (frag-direct): h0(s) @ hwN_h + P[s][:, 2048:3072]
        G(h0A + (long)(s + 1) * h0sz, H_, 0,
          WhhN + (long)s * H_ * H_, H_, 0,
          nullptr, NP, 0, P + (long)s * BATCH * NP + 2048, 0, nullptr, 0,
          cat1 + (long)s * c1sz, nullptr, h0f, nullptr,
          BATCH, H_, H_, 3, 0, 1, 0);

        // gates1 + LSTM1: [cur|h1(s-1)] @ Wcat1 + bias1 -> h1(s)
        G(cat1 + (long)s * c1sz, 1024, 0,
          Wcat1 + (long)s * H4_ * 1024, 1024, 0,
          nullptr, H4_, 0, nullptr, 0, bias1 + (long)s * H4_, 0,
          cat1 + (long)(s + 1) * c1sz, h1p + (long)s * BATCH * H1K, c1, nullptr,
          BATCH, H4_, 1024, 4, 0, 1, 0);

        cudaEventRecord(evM[s], 0);
    }

    // ---- classifier chain on sCls ----
    for (int s = 0; s < S_; ++s) {
        cudaStreamWaitEvent(sCls, evM[s], 0);
        G(h1p + (long)s * BATCH * H1K, H1K, 0,
          SHW + (long)s * SH_ * H1K, H1K, 0,
          nullptr, HIDK, 0, nullptr, 0, sh_b + (long)s * SH_, 0,
          hid + (long)s * BATCH * HIDK, nullptr, nullptr, nullptr,
          BATCH, SH_, H1K, 1, 1, 1, sCls);
        G(hid + (long)s * BATCH * HIDK, HIDK, 0,
          PW + (long)s * V_ * HIDK, HIDK, 0,
          out + (long)s * BATCH * V_, V_, 0, nullptr, 0, pred_b + (long)s * V_, 0,
          nullptr, nullptr, nullptr, nullptr, BATCH, V_, HIDK, 0, 0, 1, sCls);
    }
    cudaEventRecord(evLast, sCls);
    cudaStreamWaitEvent(0, evLast, 0);
}

// round 14
// speedup vs baseline: 1.0175x; 1.0175x over previous
#include <cuda_runtime.h>
#include <cuda_fp16.h>
#include <cstdint>

// ---------------------------------------------------------------------------
// Problem constants
// ---------------------------------------------------------------------------
#define S_   7
#define BATCH 8192
#define D_   1024
#define E_   256
#define H_   512
#define SH_  256
#define V_   100
#define D0_  1280
#define H4_  2048

typedef __half half_t;

#define H1K  1024   // h1 split hi/lo (side chain)
#define HIDK 512    // hidden split hi/lo (side chain)
#define NP   3072   // P layout: [gates0 2048 | gateN 512 | lin 512] (per row)

// ---------------------------------------------------------------------------
// Device scratch
// ---------------------------------------------------------------------------
__device__ float g_P_ih0[S_ * BATCH * H4_];      // gate-interleaved, bias folded
__device__ float g_P_NL [S_ * BATCH * 1024];     // cols 0-511 gateN(+bias), 512-1023 lin (full)
__device__ half_t g_Apre [S_ * BATCH * D0_];     // [inputs | emb_s]
__device__ half_t g_WihF [S_ * H4_ * D0_];       // W_ih0 full, gate-interleaved rows
__device__ half_t g_WNLF [S_ * 1024 * D0_];      // rows 0-511 hwN[:, :D0]; 512-1023 hwL full
__device__ half_t g_Whh0i[S_ * H4_ * H_];        // W_hh0 gate-interleaved
__device__ half_t g_WhhN [S_ * H_ * H_];         // hwN[:, D0:]
__device__ half_t g_Wcat1[S_ * H4_ * 1024];      // [W_ih1 | W_hh1] gate-interleaved
__device__ half_t g_SHW  [S_ * SH_ * H1K];       // [Wh | Wh] dup (A split)
__device__ half_t g_PW   [S_ * V_ * HIDK];       // [Wh | Wh] dup
__device__ half_t g_h0A  [(S_ + 1) * BATCH * H_];   // fp16 h0 per slot (A operand)
__device__ half_t g_cat1 [(S_ + 1) * BATCH * 1024]; // [cur | h1_prev]
__device__ half_t g_h1p  [S_ * BATCH * H1K];        // split hi/lo
__device__ half_t g_hid  [S_ * BATCH * HIDK];       // split hi/lo
__device__ float g_h0f[BATCH * H_], g_c0[BATCH * H_], g_c1[BATCH * H_];
__device__ float g_bias0[S_ * H4_], g_bias1[S_ * H4_], g_biasNL[S_ * 1024];

// ---------------------------------------------------------------------------
// PTX helpers
// ---------------------------------------------------------------------------
__device__ __forceinline__ uint32_t smem_u32(const void* p) {
    uint32_t a;
    asm("{ .reg .u64 t; cvta.to.shared.u64 t, %1; cvt.u32.u64 %0, t; }" : "=r"(a) : "l"(p));
    return a;
}
__device__ __forceinline__ uint32_t sw128(uint32_t off) { return off ^ ((off >> 3) & 0x70); }
__device__ __forceinline__ void cpa16(uint32_t dst, const void* src, int sz) {
    asm volatile("cp.async.cg.shared.global [%0], [%1], 16, %2;"
                 :: "r"(dst), "l"(src), "r"(sz) : "memory");
}
__device__ __forceinline__ void ldsm4(uint32_t* r, uint32_t addr) {
    asm volatile("ldmatrix.sync.aligned.m8n8.x4.shared.b16 {%0,%1,%2,%3}, [%4];"
                 : "=r"(r[0]), "=r"(r[1]), "=r"(r[2]), "=r"(r[3]) : "r"(addr));
}
#define MMA_F16(cc, a0, a1, a2, a3, b0, b1)                                    \
    asm volatile("mma.sync.aligned.m16n8k16.row.col.f32.f16.f16.f32 "          \
                 "{%0,%1,%2,%3}, {%4,%5,%6,%7}, {%8,%9}, {%0,%1,%2,%3};\n"     \
                 : "+f"(cc[0]), "+f"(cc[1]), "+f"(cc[2]), "+f"(cc[3])          \
                 : "r"(a0), "r"(a1), "r"(a2), "r"(a3), "r"(b0), "r"(b1))

__device__ __forceinline__ float sigm(float x) { return 1.f / (1.f + __expf(-x)); }

// ---------------------------------------------------------------------------
// Packer. second: -1 plain, 0 dup-hi at +off2, 1 residual-lo at +off2.
// gateH > 0: LSTM gate interleave remap (row r -> q*4g + 4*j + gate).
// else row remap: srcRow=(r/rps)*sDrps+sDro+(r%rps); dstRow=(r/rps)*dDrps+dDro+(r%rps)
// ---------------------------------------------------------------------------
__global__ void conv_pack(const float* __restrict__ src, long srcLd, long srcColOff,
                          long sDrps, long sDro,
                          half_t* __restrict__ dst, long dstLd, long dstColOff,
                          long dDrps, long dDro,
                          int off2, int second, int gateH,
                          long rows, int cols, long rps)
{
    int c4n = cols >> 2;
    long total = rows * c4n;
    long stride = (long)gridDim.x * blockDim.x;
    for (long t = blockIdx.x * (long)blockDim.x + threadIdx.x; t < total; t += stride) {
        long r = t / c4n;
        int  cI = (int)(t - r * c4n) << 2;
        long srow, drow;
        if (gateH > 0) {
            long u = 4L * gateH;
            long q = r / u, n = r - q * u;
            long g = n / gateH, j = n - g * gateH;
            srow = r;
            drow = q * u + 4 * j + g;
        } else {
            long rq = r / rps, rr = r - rq * rps;
            srow = rq * sDrps + sDro + rr;
            drow = rq * dDrps + dDro + rr;
        }
        float4 v = *reinterpret_cast<const float4*>(src + srow * srcLd + srcColOff + cI);
        half_t h0 = __float2half(v.x), h1 = __float2half(v.y);
        half_t h2 = __float2half(v.z), h3 = __float2half(v.w);
        long base = drow * dstLd + dstColOff + cI;
        __half2* p = (__half2*)(dst + base);
        p[0] = __halves2half2(h0, h1);
        p[1] = __halves2half2(h2, h3);
        if (second >= 0) {
            __half2* q2 = (__half2*)(dst + base + off2);
            if (second == 1) {
                half_t l0 = __float2half(v.x - __half2float(h0));
                half_t l1 = __float2half(v.y - __half2float(h1));
                half_t l2 = __float2half(v.z - __half2float(h2));
                half_t l3 = __float2half(v.w - __half2float(h3));
                q2[0] = __halves2half2(l0, l1);
                q2[1] = __halves2half2(l2, l3);
            } else {
                q2[0] = __halves2half2(h0, h1);
                q2[1] = __halves2half2(h2, h3);
            }
        }
    }
}

// Apre[s] = [inputs | emb_s]  (fp16)
__global__ void apre_build(const float* __restrict__ inputs,
                           const float* __restrict__ start,
                           const float* __restrict__ emb,
                           const int* __restrict__ labels)
{
    const long total = (long)S_ * BATCH * (D0_ / 4);
    long stride = (long)gridDim.x * blockDim.x;
    for (long t = blockIdx.x * (long)blockDim.x + threadIdx.x; t < total; t += stride) {
        int c4 = (int)(t % (D0_ / 4));
        long sb = t / (D0_ / 4);
        int b = (int)(sb % BATCH);
        int s = (int)(sb / BATCH);
        int c = c4 * 4;
        float4 v;
        if (c < D_) {
            v = *reinterpret_cast<const float4*>(inputs + (long)b * D_ + c);
        } else {
            int e = c - D_;
            if (s == 0) v = *reinterpret_cast<const float4*>(start + e);
            else {
                int lab = labels[(s - 1) * BATCH + b];
                v = *reinterpret_cast<const float4*>(emb + ((long)(s - 1) * V_ + lab) * E_ + e);
            }
        }
        __half2* p = (__half2*)(g_Apre + ((long)s * BATCH + b) * D0_ + c);
        p[0] = __halves2half2(__float2half(v.x), __float2half(v.y));
        p[1] = __halves2half2(__float2half(v.z), __float2half(v.w));
    }
}

__global__ void misc_init(const float* __restrict__ b_ih0, const float* __restrict__ b_hh0,
                          const float* __restrict__ b_ih1, const float* __restrict__ b_hh1,
                          const float* __restrict__ hwN_b0)
{
    long stride = (long)gridDim.x * blockDim.x;
    long i0 = blockIdx.x * (long)blockDim.x + threadIdx.x;
    for (long t = i0; t < S_ * H4_; t += stride) {
        long s = t / H4_, n = t % H4_;
        long j = n >> 2, g = n & 3;
        long src = s * H4_ + g * H_ + j;
        g_bias0[t] = b_ih0[src] + b_hh0[src];
        g_bias1[t] = b_ih1[src] + b_hh1[src];
    }
    for (long t = i0; t < S_ * 1024; t += stride) {
        long s = t / 1024, n = t % 1024;
        g_biasNL[t] = (n < 512) ? hwN_b0[s * H_ + n] : 0.f;
    }
}

// ---------------------------------------------------------------------------
// fp16 NT GEMM, 128x128x64 CTA tile, 8 warps (64x32 warp tiles), 3 stages.
// modes: 0 fp32 C; 1 packed split fp16 (hid); 2 LSTM0; 3 HWY (frag-direct);
//        4 LSTM1.
// ---------------------------------------------------------------------------
#define BM 128
#define BN 128
#define BK 64
#define STG_BYTES 16384
#define SMEM_GEMM (6 * STG_BYTES)

__global__ __launch_bounds__(256, 2)
void gemm_mma(const half_t* __restrict__ A, int lda, long sA,
              const half_t* __restrict__ B, int ldb, long sB,
              float* __restrict__ C, int ldc, long sC,
              const float* __restrict__ Cin, long sCin,
              const float* __restrict__ bias, long sBias,
              half_t* __restrict__ O1, half_t* __restrict__ O2,
              float* __restrict__ X1, float* __restrict__ X2,
              int M, int N, int K, int mode, int relu)
{
    extern __shared__ char smem[];
    const uint32_t sbA = smem_u32(smem);
    const uint32_t sbB = sbA + 3 * STG_BYTES;

    const int z = blockIdx.z;
    A += z * sA;  B += z * sB;
    if (C)    C    += z * sC;
    if (Cin)  Cin  += z * sCin;
    if (bias) bias += z * sBias;

    const int tid = threadIdx.x;
    const int warp = tid >> 5, lane = tid & 31;
    const int m0 = blockIdx.y * BM, n0 = blockIdx.x * BN;
    const int wm = (warp & 1) * 64, wn = (warp >> 1) * 32;

    float c[4][4][4];
#pragma unroll
    for (int i = 0; i < 4; ++i)
#pragma unroll
        for (int j = 0; j < 4; ++j)
#pragma unroll
            for (int r = 0; r < 4; ++r) c[i][j][r] = 0.f;

    const int kT = K / BK;

    auto issue = [&](int t) {
        const int kk = t * BK;
        const uint32_t aBuf = sbA + (t % 3) * STG_BYTES;
        const uint32_t bBuf = sbB + (t % 3) * STG_BYTES;
#pragma unroll
        for (int w = 0; w < 4; ++w) {
            int g = tid + w * 256;
            int row = g >> 3, q = g & 7;
            const char* srcA = (const char*)(A + (long)(m0 + row) * lda + kk) + q * 16;
            cpa16(aBuf + sw128(row * 128 + q * 16), srcA, 16);
        }
#pragma unroll
        for (int w = 0; w < 4; ++w) {
            int g = tid + w * 256;
            int row = g >> 3, q = g & 7;
            int n = n0 + row;
            const char* srcB = (const char*)(B + (long)n * ldb + kk) + q * 16;
            cpa16(bBuf + sw128(row * 128 + q * 16), (n < N) ? srcB : (const char*)B,
                  (n < N) ? 16 : 0);
        }
        asm volatile("cp.async.commit_group;" ::: "memory");
    };

    issue(0);
    if (kT > 1) issue(1);

    for (int t = 0; t < kT; ++t) {
        if (t + 1 < kT) asm volatile("cp.async.wait_group 1;" ::: "memory");
        else            asm volatile("cp.async.wait_group 0;" ::: "memory");
        __syncthreads();
        if (t + 2 < kT) issue(t + 2);

        const uint32_t aS = sbA + (t % 3) * STG_BYTES;
        const uint32_t bS = sbB + (t % 3) * STG_BYTES;
#pragma unroll
        for (int ks = 0; ks < 4; ++ks) {
            uint32_t a[4][4], b[2][4];
            const int colByte = (ks * 16 + ((lane >> 4) << 3)) * 2;
#pragma unroll
            for (int i = 0; i < 4; ++i)
                ldsm4(a[i], aS + sw128((wm + i * 16 + (lane & 15)) * 128 + colByte));
#pragma unroll
            for (int jb = 0; jb < 2; ++jb)
                ldsm4(b[jb], bS + sw128((wn + jb * 16 + (lane & 15)) * 128 + colByte));
#pragma unroll
            for (int i = 0; i < 4; ++i)
#pragma unroll
                for (int j = 0; j < 4; ++j) {
                    const int jb = j >> 1, sel = j & 1;
                    MMA_F16(c[i][j], a[i][0], a[i][1], a[i][2], a[i][3],
                            b[jb][sel], b[jb][sel + 2]);
                }
        }
    }

    if (mode != 2 && mode != 4) {
        // fragment-direct epilogues: 0 (fp32 C), 1 (split hid), 3 (highway)
#pragma unroll
        for (int i = 0; i < 4; ++i) {
#pragma unroll
            for (int rr = 0; rr < 2; ++rr) {
                const int m = m0 + wm + i * 16 + (lane >> 2) + rr * 8;
#pragma unroll
                for (int j = 0; j < 4; ++j) {
                    const int n = n0 + wn + j * 8 + (lane & 3) * 2;
                    if (n < N) {
                        float v0 = c[i][j][rr * 2 + 0];
                        float v1 = c[i][j][rr * 2 + 1];
                        if (mode == 3) {
                            // highway: gN = acc + P_NL[:, n]; lin = P_NL[:, 512+n]
                            const long ci = (long)m * 1024 + n;
                            const float g0 = sigm(v0 + Cin[ci]);
                            const float g1 = sigm(v1 + Cin[ci + 1]);
                            const float l0 = Cin[ci + 512];
                            const float l1 = Cin[ci + 513];
                            const long hx = (long)m * H_ + n;
                            const float cur0 = g0 * X1[hx]     + (1.f - g0) * l0;
                            const float cur1 = g1 * X1[hx + 1] + (1.f - g1) * l1;
                            *(__half2*)(O1 + (long)m * 1024 + n) =
                                __halves2half2(__float2half(cur0), __float2half(cur1));
                        } else {
                            if (bias) { v0 += bias[n]; v1 += bias[n + 1]; }
                            const long idx = (long)m * ldc + n;
                            if (Cin) { v0 += Cin[idx]; v1 += Cin[idx + 1]; }
                            if (relu) { v0 = fmaxf(v0, 0.f); v1 = fmaxf(v1, 0.f); }
                            if (mode == 1) {
                                const long o = (long)m * HIDK + n;
                                half_t h0 = __float2half(v0), h1 = __float2half(v1);
                                half_t l0 = __float2half(v0 - __half2float(h0));
                                half_t l1 = __float2half(v1 - __half2float(h1));
                                *(__half2*)(O1 + o)       = __halves2half2(h0, h1);
                                *(__half2*)(O1 + o + 256) = __halves2half2(l0, l1);
                            } else {
                                float2 st; st.x = v0; st.y = v1;
                                *(float2*)(C + idx) = st;
                            }
                        }
                    }
                }
            }
        }
    } else {
        // LSTM epilogues via smem staging (gate-interleaved N)
        __syncthreads();
        float* sAcc = (float*)smem;
#pragma unroll
        for (int i = 0; i < 4; ++i)
#pragma unroll
            for (int j = 0; j < 4; ++j)
#pragma unroll
                for (int rr = 0; rr < 2; ++rr)
#pragma unroll
                    for (int cc = 0; cc < 2; ++cc)
                        sAcc[(wm + i * 16 + (lane >> 2) + rr * 8) * 132 +
                             wn + j * 8 + (lane & 3) * 2 + cc] = c[i][j][rr * 2 + cc];
        __syncthreads();

        const int jbase = n0 >> 2;
        for (int t2 = tid; t2 < 128 * 32; t2 += 256) {
            const int row = t2 >> 5, jj = t2 & 31;
            const int b = m0 + row, j = jbase + jj;
            float gv[4];
#pragma unroll
            for (int g = 0; g < 4; ++g) {
                float x = sAcc[row * 132 + 4 * jj + g];
                if (mode == 2) x += Cin[(long)b * ldc + n0 + 4 * jj + g];
                else           x += bias[n0 + 4 * jj + g];
                gv[g] = x;
            }
            const float ig = sigm(gv[0]), fg = sigm(gv[1]);
            const float gg = tanhf(gv[2]), og = sigm(gv[3]);
            const long sidx = (long)b * H_ + j;
            const float cn = fg * X1[sidx] + ig * gg;
            const float hn = og * tanhf(cn);
            X1[sidx] = cn;
            half_t hh = __float2half(hn);
            if (mode == 2) {
                X2[sidx] = hn;                       // h0 fp32 for highway
                O1[(long)b * H_ + j] = hh;           // h0A[s+1]
            } else {
                O1[(long)b * 1024 + 512 + j] = hh;   // cat1[s+1] h1 cols
                half_t hl = __float2half(hn - __half2float(hh));
                const long o2 = (long)b * H1K + j;
                O2[o2] = hh; O2[o2 + 512] = hl;      // h1p[s] split
            }
        }
    }
}

// ---------------------------------------------------------------------------
// Host
// ---------------------------------------------------------------------------
#define SYM(var, sym) cudaGetSymbolAddress((void**)&var, sym)

static inline void G(const half_t* A, int lda, long sA,
                     const half_t* B, int ldb, long sB,
                     float* C, int ldc, long sC,
                     const float* Cin, long sCin,
                     const float* bias, long sBias,
                     half_t* O1, half_t* O2, float* X1, float* X2,
                     int M, int N, int K, int mode, int relu, int Z,
                     cudaStream_t st)
{
    dim3 grid((N + BN - 1) / BN, M / BM, Z);
    gemm_mma<<<grid, 256, SMEM_GEMM, st>>>(A, lda, sA, B, ldb, sB, C, ldc, sC,
                                           Cin, sCin, bias, sBias, O1, O2, X1, X2,
                                           M, N, K, mode, relu);
}

extern "C" void kernel_launch(void* const* d_in, const int* in_sizes, int n_in,
                              void* d_out, int out_size)
{
    const float* inputs = (const float*)d_in[0];
    const int*   labels = (const int*)  d_in[1];
    const float* start  = (const float*)d_in[2];
    const float* emb    = (const float*)d_in[3];
    const float* W_ih0  = (const float*)d_in[4];
    const float* W_hh0  = (const float*)d_in[5];
    const float* b_ih0  = (const float*)d_in[6];
    const float* b_hh0  = (const float*)d_in[7];
    const float* hwN_W0 = (const float*)d_in[8];
    const float* hwN_b0 = (const float*)d_in[9];
    const float* hwL_W0 = (const float*)d_in[10];
    const float* W_ih1  = (const float*)d_in[11];
    const float* W_hh1  = (const float*)d_in[12];
    const float* b_ih1  = (const float*)d_in[13];
    const float* b_hh1  = (const float*)d_in[14];
    // d_in[15..17] dead in reference (layer-1 highway output unused)
    const float* sh_W   = (const float*)d_in[18];
    const float* sh_b   = (const float*)d_in[19];
    const float* pred_W = (const float*)d_in[20];
    const float* pred_b = (const float*)d_in[21];
    float* out = (float*)d_out;

    static cudaStream_t sPre = nullptr, sCls = nullptr;
    static cudaEvent_t evSetup, evPa[S_], evPb[S_], evM[S_], evLast;
    if (!sPre) {
        int lo, hi;
        cudaDeviceGetStreamPriorityRange(&lo, &hi);   // lo = lowest priority
        cudaStreamCreateWithPriority(&sPre, cudaStreamNonBlocking, lo);
        cudaStreamCreateWithPriority(&sCls, cudaStreamNonBlocking, lo);
        cudaEventCreateWithFlags(&evSetup, cudaEventDisableTiming);
        cudaEventCreateWithFlags(&evLast, cudaEventDisableTiming);
        for (int i = 0; i < S_; ++i) {
            cudaEventCreateWithFlags(&evPa[i], cudaEventDisableTiming);
            cudaEventCreateWithFlags(&evPb[i], cudaEventDisableTiming);
            cudaEventCreateWithFlags(&evM[i], cudaEventDisableTiming);
        }
        cudaFuncSetAttribute(gemm_mma, cudaFuncAttributeMaxDynamicSharedMemorySize,
                             SMEM_GEMM);
    }

    float *P_ih0, *P_NL, *bias0, *bias1, *biasNL, *h0f, *c0, *c1;
    half_t *Apre, *WihF, *WNLF, *Whh0i, *WhhN, *Wcat1, *SHW, *PW;
    half_t *h0A, *cat1, *h1p, *hid;
    SYM(P_ih0, g_P_ih0); SYM(P_NL, g_P_NL);
    SYM(bias0, g_bias0); SYM(bias1, g_bias1); SYM(biasNL, g_biasNL);
    SYM(h0f, g_h0f); SYM(c0, g_c0); SYM(c1, g_c1);
    SYM(Apre, g_Apre); SYM(WihF, g_WihF); SYM(WNLF, g_WNLF);
    SYM(Whh0i, g_Whh0i); SYM(WhhN, g_WhhN); SYM(Wcat1, g_Wcat1);
    SYM(SHW, g_SHW); SYM(PW, g_PW);
    SYM(h0A, g_h0A); SYM(cat1, g_cat1); SYM(h1p, g_h1p); SYM(hid, g_hid);

    const long h0sz = (long)BATCH * H_;
    const long c1sz = (long)BATCH * 1024;
    const int CB = 2048;
    const long BIGR = 1L << 40;

    // ---- init ----
    cudaMemsetAsync(c0, 0, h0sz * 4);
    cudaMemsetAsync(c1, 0, h0sz * 4);
    cudaMemsetAsync(h0A, 0, h0sz * 2);    // slot-0 h0
    cudaMemsetAsync(cat1, 0, c1sz * 2);   // slot-0 [cur|h1]

    // ---- pack weights (stream 0) ----
    conv_pack<<<CB, 256>>>(W_ih0, D0_, 0, 0, 0, WihF, D0_, 0, 0, 0, 0, -1, H_,
                           (long)S_ * H4_, D0_, BIGR);
    conv_pack<<<CB, 256>>>(W_hh0, H_, 0, 0, 0, Whh0i, H_, 0, 0, 0, 0, -1, H_,
                           (long)S_ * H4_, H_, BIGR);
    conv_pack<<<CB, 256>>>(W_ih1, H_, 0, 0, 0, Wcat1, 1024, 0, 0, 0, 0, -1, H_,
                           (long)S_ * H4_, H_, BIGR);
    conv_pack<<<CB, 256>>>(W_hh1, H_, 0, 0, 0, Wcat1, 1024, 512, 0, 0, 0, -1, H_,
                           (long)S_ * H4_, H_, BIGR);
    conv_pack<<<CB, 256>>>(hwN_W0, D0_ + H_, 0, H_, 0, WNLF, D0_, 0, 1024, 0,
                           0, -1, 0, (long)S_ * H_, D0_, H_);
    conv_pack<<<CB, 256>>>(hwL_W0, D0_, 0, H_, 0, WNLF, D0_, 0, 1024, 512,
                           0, -1, 0, (long)S_ * H_, D0_, H_);
    conv_pack<<<CB, 256>>>(hwN_W0, D0_ + H_, D0_, 0, 0, WhhN, H_, 0, 0, 0,
                           0, -1, 0, (long)S_ * H_, H_, BIGR);
    conv_pack<<<CB, 256>>>(sh_W, H_, 0, 0, 0, SHW, H1K, 0, 0, 0, 512, 0, 0,
                           (long)S_ * SH_, H_, BIGR);
    conv_pack<<<CB, 256>>>(pred_W, SH_, 0, 0, 0, PW, HIDK, 0, 0, 0, 256, 0, 0,
                           (long)S_ * V_, SH_, BIGR);
    apre_build<<<CB, 256>>>(inputs, start, emb, labels);
    misc_init<<<CB, 256>>>(b_ih0, b_hh0, b_ih1, b_hh1, hwN_b0);
    cudaEventRecord(evSetup, 0);

    // ---- per-slot precompute on low-priority stream (overlaps serial chain) ----
    cudaStreamWaitEvent(sPre, evSetup, 0);
    for (int s = 0; s < S_; ++s) {
        // P_ih0[s] = Apre[s] @ W_ih0_full[s].T + bias0[s]   (gate-interleaved N)
        G(Apre + (long)s * BATCH * D0_, D0_, 0,
          WihF + (long)s * H4_ * D0_, D0_, 0,
          P_ih0 + (long)s * BATCH * H4_, H4_, 0, nullptr, 0,
          bias0 + (long)s * H4_, 0,
          nullptr, nullptr, nullptr, nullptr, BATCH, H4_, D0_, 0, 0, 1, sPre);
        cudaEventRecord(evPa[s], sPre);
        // P_NL[s] = Apre[s] @ [hwN_D0 | hwL_full][s].T + [bN | 0]
        G(Apre + (long)s * BATCH * D0_, D0_, 0,
          WNLF + (long)s * 1024 * D0_, D0_, 0,
          P_NL + (long)s * BATCH * 1024, 1024, 0, nullptr, 0,
          biasNL + (long)s * 1024, 0,
          nullptr, nullptr, nullptr, nullptr, BATCH, 1024, D0_, 0, 0, 1, sPre);
        cudaEventRecord(evPb[s], sPre);
    }

    // ---- serial chain on main stream ----
    for (int s = 0; s < S_; ++s) {
        cudaStreamWaitEvent(0, evPa[s], 0);
        // gates0 + LSTM0: h0(s-1) @ W_hh0 + P_ih0[s]  -> h0(s)
        G(h0A + (long)s * h0sz, H_, 0,
          Whh0i + (long)s * H4_ * H_, H_, 0,
          nullptr, H4_, 0, P_ih0 + (long)s * BATCH * H4_, 0, nullptr, 0,
          h0A + (long)(s + 1) * h0sz, nullptr, c0, h0f,
          BATCH, H4_, H_, 2, 0, 1, 0);

        cudaStreamWaitEvent(0, evPb[s], 0);
        // gateN + highway (frag-direct): h0(s) @ hwN_h + P_NL[s] -> cur into cat1[s]
        G(h0A + (long)(s + 1) * h0sz, H_, 0,
          WhhN + (long)s * H_ * H_, H_, 0,
          nullptr, 1024, 0, P_NL + (long)s * BATCH * 1024, 0, nullptr, 0,
          cat1 + (long)s * c1sz, nullptr, h0f, nullptr,
          BATCH, H_, H_, 3, 0, 1, 0);

        // gates1 + LSTM1: [cur|h1(s-1)] @ Wcat1 + bias1 -> h1(s)
        G(cat1 + (long)s * c1sz, 1024, 0,
          Wcat1 + (long)s * H4_ * 1024, 1024, 0,
          nullptr, H4_, 0, nullptr, 0, bias1 + (long)s * H4_, 0,
          cat1 + (long)(s + 1) * c1sz, h1p + (long)s * BATCH * H1K, c1, nullptr,
          BATCH, H4_, 1024, 4, 0, 1, 0);

        cudaEventRecord(evM[s], 0);
    }

    // ---- classifier chain on second low-priority stream ----
    for (int s = 0; s < S_; ++s) {
        cudaStreamWaitEvent(sCls, evM[s], 0);
        G(h1p + (long)s * BATCH * H1K, H1K, 0,
          SHW + (long)s * SH_ * H1K, H1K, 0,
          nullptr, HIDK, 0, nullptr, 0, sh_b + (long)s * SH_, 0,
          hid + (long)s * BATCH * HIDK, nullptr, nullptr, nullptr,
          BATCH, SH_, H1K, 1, 1, 1, sCls);
        G(hid + (long)s * BATCH * HIDK, HIDK, 0,
          PW + (long)s * V_ * HIDK, HIDK, 0,
          out + (long)s * BATCH * V_, V_, 0, nullptr, 0, pred_b + (long)s * V_, 0,
          nullptr, nullptr, nullptr, nullptr, BATCH, V_, HIDK, 0, 0, 1, sCls);
    }
    cudaEventRecord(evLast, sCls);
    cudaStreamWaitEvent(0, evLast, 0);
}

// round 16
// speedup vs baseline: 1.0437x; 1.0258x over previous
#include <cuda_runtime.h>
#include <cuda_fp16.h>
#include <cstdint>

// ---------------------------------------------------------------------------
// Problem constants
// ---------------------------------------------------------------------------
#define S_   7
#define BATCH 8192
#define D_   1024
#define E_   256
#define H_   512
#define SH_  256
#define V_   100
#define D0_  1280
#define H4_  2048

typedef __half half_t;

#define H1K  1024   // h1 split hi/lo (side chain)
#define HIDK 512    // hidden split hi/lo (side chain)
#define NW   3072   // We cols: [gates0 2048 (gate-ilv) | gateN 512 | lin 512]

// ---------------------------------------------------------------------------
// Device scratch
// ---------------------------------------------------------------------------
__device__ float g_P_ih0[S_ * BATCH * H4_];      // gate-interleaved (bias via We)
__device__ float g_P_NL [S_ * BATCH * 1024];     // cols 0-511 gateN, 512-1023 lin
__device__ float g_We   [S_ * 128 * NW];         // per-label emb contributions + bias
__device__ half_t g_embA [S_ * 128 * E_];        // emb vocab rows (slot0: start @ row 0)
__device__ half_t g_WembA[S_ * NW * E_];         // [Wih0_emb ilv | hwN_emb | hwL_emb]
__device__ half_t g_INP  [BATCH * D_];           // inputs fp16
__device__ half_t g_WihD [S_ * H4_ * D_];        // W_ih0[:, :D] gate-interleaved
__device__ half_t g_WNLD [S_ * 1024 * D_];       // rows 0-511 hwN[:, :D]; 512-1023 hwL[:, :D]
__device__ half_t g_Whh0i[S_ * H4_ * H_];        // W_hh0 gate-interleaved
__device__ half_t g_WhhN [S_ * H_ * H_];         // hwN[:, D0:]
__device__ half_t g_Wcat1[S_ * H4_ * 1024];      // [W_ih1 | W_hh1] gate-interleaved
__device__ half_t g_SHW  [S_ * SH_ * H1K];       // [Wh | Wh] dup (A split)
__device__ half_t g_PW   [S_ * V_ * HIDK];       // [Wh | Wh] dup
__device__ half_t g_h0A  [(S_ + 1) * BATCH * H_];
__device__ half_t g_cat1 [(S_ + 1) * BATCH * 1024];
__device__ half_t g_h1p  [S_ * BATCH * H1K];
__device__ half_t g_hid  [S_ * BATCH * HIDK];
__device__ float g_h0f[BATCH * H_], g_c0[BATCH * H_], g_c1[BATCH * H_];
__device__ float g_biasAll[S_ * NW], g_bias1[S_ * H4_];
__device__ int   g_labAll[S_ * BATCH];

// ---------------------------------------------------------------------------
// PTX helpers
// ---------------------------------------------------------------------------
__device__ __forceinline__ uint32_t smem_u32(const void* p) {
    uint32_t a;
    asm("{ .reg .u64 t; cvta.to.shared.u64 t, %1; cvt.u32.u64 %0, t; }" : "=r"(a) : "l"(p));
    return a;
}
__device__ __forceinline__ uint32_t sw128(uint32_t off) { return off ^ ((off >> 3) & 0x70); }
__device__ __forceinline__ void cpa16(uint32_t dst, const void* src, int sz) {
    asm volatile("cp.async.cg.shared.global [%0], [%1], 16, %2;"
                 :: "r"(dst), "l"(src), "r"(sz) : "memory");
}
__device__ __forceinline__ void ldsm4(uint32_t* r, uint32_t addr) {
    asm volatile("ldmatrix.sync.aligned.m8n8.x4.shared.b16 {%0,%1,%2,%3}, [%4];"
                 : "=r"(r[0]), "=r"(r[1]), "=r"(r[2]), "=r"(r[3]) : "r"(addr));
}
#define MMA_F16(cc, a0, a1, a2, a3, b0, b1)                                    \
    asm volatile("mma.sync.aligned.m16n8k16.row.col.f32.f16.f16.f32 "          \
                 "{%0,%1,%2,%3}, {%4,%5,%6,%7}, {%8,%9}, {%0,%1,%2,%3};\n"     \
                 : "+f"(cc[0]), "+f"(cc[1]), "+f"(cc[2]), "+f"(cc[3])          \
                 : "r"(a0), "r"(a1), "r"(a2), "r"(a3), "r"(b0), "r"(b1))

__device__ __forceinline__ float sigm(float x) { return 1.f / (1.f + __expf(-x)); }

// ---------------------------------------------------------------------------
// Packer. second: -1 plain, 0 dup-hi at +off2, 1 residual-lo at +off2.
// gateH > 0: gate interleave (r -> (r/(4g))*dDrps + 4*(r%...)+gate), dDrps = dst rows/slot.
// else: srcRow=(r/rps)*sDrps+sDro+(r%rps); dstRow=(r/rps)*dDrps+dDro+(r%rps)
// ---------------------------------------------------------------------------
__global__ void conv_pack(const float* __restrict__ src, long srcLd, long srcColOff,
                          long sDrps, long sDro,
                          half_t* __restrict__ dst, long dstLd, long dstColOff,
                          long dDrps, long dDro,
                          int off2, int second, int gateH,
                          long rows, int cols, long rps)
{
    int c4n = cols >> 2;
    long total = rows * c4n;
    long stride = (long)gridDim.x * blockDim.x;
    for (long t = blockIdx.x * (long)blockDim.x + threadIdx.x; t < total; t += stride) {
        long r = t / c4n;
        int  cI = (int)(t - r * c4n) << 2;
        long srow, drow;
        if (gateH > 0) {
            long u = 4L * gateH;
            long q = r / u, n = r - q * u;
            long g = n / gateH, j = n - g * gateH;
            srow = r;
            drow = q * dDrps + 4 * j + g;
        } else {
            long rq = r / rps, rr = r - rq * rps;
            srow = rq * sDrps + sDro + rr;
            drow = rq * dDrps + dDro + rr;
        }
        float4 v = *reinterpret_cast<const float4*>(src + srow * srcLd + srcColOff + cI);
        half_t h0 = __float2half(v.x), h1 = __float2half(v.y);
        half_t h2 = __float2half(v.z), h3 = __float2half(v.w);
        long base = drow * dstLd + dstColOff + cI;
        __half2* p = (__half2*)(dst + base);
        p[0] = __halves2half2(h0, h1);
        p[1] = __halves2half2(h2, h3);
        if (second >= 0) {
            __half2* q2 = (__half2*)(dst + base + off2);
            if (second == 1) {
                half_t l0 = __float2half(v.x - __half2float(h0));
                half_t l1 = __float2half(v.y - __half2float(h1));
                half_t l2 = __float2half(v.z - __half2float(h2));
                half_t l3 = __float2half(v.w - __half2float(h3));
                q2[0] = __halves2half2(l0, l1);
                q2[1] = __halves2half2(l2, l3);
            } else {
                q2[0] = __halves2half2(h0, h1);
                q2[1] = __halves2half2(h2, h3);
            }
        }
    }
}

// embA[s][r][e]: slot0: row0=start, rows>0=0; slot s>0: rows<V = emb[s-1][r], else 0
__global__ void emba_build(const float* __restrict__ start,
                           const float* __restrict__ emb)
{
    const long total = (long)S_ * 128 * E_;
    long stride = (long)gridDim.x * blockDim.x;
    for (long t = blockIdx.x * (long)blockDim.x + threadIdx.x; t < total; t += stride) {
        int e = (int)(t % E_);
        int r = (int)((t / E_) % 128);
        int s = (int)(t / (128L * E_));
        float v = 0.f;
        if (s == 0) { if (r == 0) v = start[e]; }
        else if (r < V_) v = emb[((long)(s - 1) * V_ + r) * E_ + e];
        g_embA[t] = __float2half(v);
    }
}

__global__ void misc_init(const float* __restrict__ b_ih0, const float* __restrict__ b_hh0,
                          const float* __restrict__ b_ih1, const float* __restrict__ b_hh1,
                          const float* __restrict__ hwN_b0,
                          const int* __restrict__ labels)
{
    long stride = (long)gridDim.x * blockDim.x;
    long i0 = blockIdx.x * (long)blockDim.x + threadIdx.x;
    for (long t = i0; t < S_ * NW; t += stride) {
        long s = t / NW, n = t % NW;
        float v;
        if (n < 2048) {           // gates0, gate-interleaved
            long j = n >> 2, g = n & 3;
            long src = s * H4_ + g * H_ + j;
            v = b_ih0[src] + b_hh0[src];
        } else if (n < 2560) {    // gateN
            v = hwN_b0[s * H_ + (n - 2048)];
        } else {                  // lin
            v = 0.f;
        }
        g_biasAll[t] = v;
    }
    for (long t = i0; t < S_ * H4_; t += stride) {
        long s = t / H4_, n = t % H4_;
        long j = n >> 2, g = n & 3;
        long src = s * H4_ + g * H_ + j;
        g_bias1[t] = b_ih1[src] + b_hh1[src];
    }
    for (long t = i0; t < (long)S_ * BATCH; t += stride) {
        long s = t / BATCH, b = t % BATCH;
        g_labAll[t] = (s == 0) ? 0 : labels[(s - 1) * BATCH + b];
    }
}

// ---------------------------------------------------------------------------
// fp16 NT GEMM, 128x128x64 CTA tile, 8 warps (64x32 warp tiles), 3 stages.
// modes: 0 fp32 C (+bias | +label-gather We-row via lab/Cin | +Cin, relu);
//        1 packed split fp16 (hid); 2 LSTM0; 3 HWY (frag-direct); 4 LSTM1.
// ---------------------------------------------------------------------------
#define BM 128
#define BN 128
#define BK 64
#define STG_BYTES 16384
#define SMEM_GEMM (6 * STG_BYTES)

__global__ __launch_bounds__(256, 2)
void gemm_mma(const half_t* __restrict__ A, int lda, long sA,
              const half_t* __restrict__ B, int ldb, long sB,
              float* __restrict__ C, int ldc, long sC,
              const float* __restrict__ Cin, long sCin,
              const float* __restrict__ bias, long sBias,
              const int* __restrict__ lab,
              half_t* __restrict__ O1, half_t* __restrict__ O2,
              float* __restrict__ X1, float* __restrict__ X2,
              int M, int N, int K, int mode, int relu)
{
    extern __shared__ char smem[];
    const uint32_t sbA = smem_u32(smem);
    const uint32_t sbB = sbA + 3 * STG_BYTES;

    const int z = blockIdx.z;
    A += z * sA;  B += z * sB;
    if (C)    C    += z * sC;
    if (Cin)  Cin  += z * sCin;
    if (bias) bias += z * sBias;

    const int tid = threadIdx.x;
    const int warp = tid >> 5, lane = tid & 31;
    const int m0 = blockIdx.y * BM, n0 = blockIdx.x * BN;
    const int wm = (warp & 1) * 64, wn = (warp >> 1) * 32;

    float c[4][4][4];
#pragma unroll
    for (int i = 0; i < 4; ++i)
#pragma unroll
        for (int j = 0; j < 4; ++j)
#pragma unroll
            for (int r = 0; r < 4; ++r) c[i][j][r] = 0.f;

    const int kT = K / BK;

    auto issue = [&](int t) {
        const int kk = t * BK;
        const uint32_t aBuf = sbA + (t % 3) * STG_BYTES;
        const uint32_t bBuf = sbB + (t % 3) * STG_BYTES;
#pragma unroll
        for (int w = 0; w < 4; ++w) {
            int g = tid + w * 256;
            int row = g >> 3, q = g & 7;
            const char* srcA = (const char*)(A + (long)(m0 + row) * lda + kk) + q * 16;
            cpa16(aBuf + sw128(row * 128 + q * 16), srcA, 16);
        }
#pragma unroll
        for (int w = 0; w < 4; ++w) {
            int g = tid + w * 256;
            int row = g >> 3, q = g & 7;
            int n = n0 + row;
            const char* srcB = (const char*)(B + (long)n * ldb + kk) + q * 16;
            cpa16(bBuf + sw128(row * 128 + q * 16), (n < N) ? srcB : (const char*)B,
                  (n < N) ? 16 : 0);
        }
        asm volatile("cp.async.commit_group;" ::: "memory");
    };

    issue(0);
    if (kT > 1) issue(1);

    for (int t = 0; t < kT; ++t) {
        if (t + 1 < kT) asm volatile("cp.async.wait_group 1;" ::: "memory");
        else            asm volatile("cp.async.wait_group 0;" ::: "memory");
        __syncthreads();
        if (t + 2 < kT) issue(t + 2);

        const uint32_t aS = sbA + (t % 3) * STG_BYTES;
        const uint32_t bS = sbB + (t % 3) * STG_BYTES;
#pragma unroll
        for (int ks = 0; ks < 4; ++ks) {
            uint32_t a[4][4], b[2][4];
            const int colByte = (ks * 16 + ((lane >> 4) << 3)) * 2;
#pragma unroll
            for (int i = 0; i < 4; ++i)
                ldsm4(a[i], aS + sw128((wm + i * 16 + (lane & 15)) * 128 + colByte));
#pragma unroll
            for (int jb = 0; jb < 2; ++jb)
                ldsm4(b[jb], bS + sw128((wn + jb * 16 + (lane & 15)) * 128 + colByte));
#pragma unroll
            for (int i = 0; i < 4; ++i)
#pragma unroll
                for (int j = 0; j < 4; ++j) {
                    const int jb = j >> 1, sel = j & 1;
                    MMA_F16(c[i][j], a[i][0], a[i][1], a[i][2], a[i][3],
                            b[jb][sel], b[jb][sel + 2]);
                }
        }
    }

    if (mode != 2 && mode != 4) {
        // fragment-direct epilogues: 0 (fp32 C), 1 (split hid), 3 (highway)
#pragma unroll
        for (int i = 0; i < 4; ++i) {
#pragma unroll
            for (int rr = 0; rr < 2; ++rr) {
                const int m = m0 + wm + i * 16 + (lane >> 2) + rr * 8;
#pragma unroll
                for (int j = 0; j < 4; ++j) {
                    const int n = n0 + wn + j * 8 + (lane & 3) * 2;
                    if (n < N) {
                        float v0 = c[i][j][rr * 2 + 0];
                        float v1 = c[i][j][rr * 2 + 1];
                        if (mode == 3) {
                            // highway: gN = acc + P_NL[:, n]; lin = P_NL[:, 512+n]
                            const long ci = (long)m * 1024 + n;
                            const float g0 = sigm(v0 + Cin[ci]);
                            const float g1 = sigm(v1 + Cin[ci + 1]);
                            const float l0 = Cin[ci + 512];
                            const float l1 = Cin[ci + 513];
                            const long hx = (long)m * H_ + n;
                            const float cur0 = g0 * X1[hx]     + (1.f - g0) * l0;
                            const float cur1 = g1 * X1[hx + 1] + (1.f - g1) * l1;
                            *(__half2*)(O1 + (long)m * 1024 + n) =
                                __halves2half2(__float2half(cur0), __float2half(cur1));
                        } else {
                            if (bias) { v0 += bias[n]; v1 += bias[n + 1]; }
                            const long idx = (long)m * ldc + n;
                            if (lab) {
                                const float* wr = Cin + (long)lab[m] * NW;
                                v0 += wr[n]; v1 += wr[n + 1];
                            } else if (Cin) {
                                v0 += Cin[idx]; v1 += Cin[idx + 1];
                            }
                            if (relu) { v0 = fmaxf(v0, 0.f); v1 = fmaxf(v1, 0.f); }
                            if (mode == 1) {
                                const long o = (long)m * HIDK + n;
                                half_t h0 = __float2half(v0), h1 = __float2half(v1);
                                half_t l0 = __float2half(v0 - __half2float(h0));
                                half_t l1 = __float2half(v1 - __half2float(h1));
                                *(__half2*)(O1 + o)       = __halves2half2(h0, h1);
                                *(__half2*)(O1 + o + 256) = __halves2half2(l0, l1);
                            } else {
                                float2 st; st.x = v0; st.y = v1;
                                *(float2*)(C + idx) = st;
                            }
                        }
                    }
                }
            }
        }
    } else {
        // LSTM epilogues via smem staging (gate-interleaved N)
        __syncthreads();
        float* sAcc = (float*)smem;
#pragma unroll
        for (int i = 0; i < 4; ++i)
#pragma unroll
            for (int j = 0; j < 4; ++j)
#pragma unroll
                for (int rr = 0; rr < 2; ++rr)
#pragma unroll
                    for (int cc = 0; cc < 2; ++cc)
                        sAcc[(wm + i * 16 + (lane >> 2) + rr * 8) * 132 +
                             wn + j * 8 + (lane & 3) * 2 + cc] = c[i][j][rr * 2 + cc];
        __syncthreads();

        const int jbase = n0 >> 2;
        for (int t2 = tid; t2 < 128 * 32; t2 += 256) {
            const int row = t2 >> 5, jj = t2 & 31;
            const int b = m0 + row, j = jbase + jj;
            float gv[4];
#pragma unroll
            for (int g = 0; g < 4; ++g) {
                float x = sAcc[row * 132 + 4 * jj + g];
                if (mode == 2) x += Cin[(long)b * ldc + n0 + 4 * jj + g];
                else           x += bias[n0 + 4 * jj + g];
                gv[g] = x;
            }
            const float ig = sigm(gv[0]), fg = sigm(gv[1]);
            const float gg = tanhf(gv[2]), og = sigm(gv[3]);
            const long sidx = (long)b * H_ + j;
            const float cn = fg * X1[sidx] + ig * gg;
            const float hn = og * tanhf(cn);
            X1[sidx] = cn;
            half_t hh = __float2half(hn);
            if (mode == 2) {
                X2[sidx] = hn;                       // h0 fp32 for highway
                O1[(long)b * H_ + j] = hh;           // h0A[s+1]
            } else {
                O1[(long)b * 1024 + 512 + j] = hh;   // cat1[s+1] h1 cols
                half_t hl = __float2half(hn - __half2float(hh));
                const long o2 = (long)b * H1K + j;
                O2[o2] = hh; O2[o2 + 512] = hl;      // h1p[s] split
            }
        }
    }
}

// ---------------------------------------------------------------------------
// Host
// ---------------------------------------------------------------------------
#define SYM(var, sym) cudaGetSymbolAddress((void**)&var, sym)

static inline void G(const half_t* A, int lda, long sA,
                     const half_t* B, int ldb, long sB,
                     float* C, int ldc, long sC,
                     const float* Cin, long sCin,
                     const float* bias, long sBias,
                     const int* lab,
                     half_t* O1, half_t* O2, float* X1, float* X2,
                     int M, int N, int K, int mode, int relu, int Z,
                     cudaStream_t st)
{
    dim3 grid((N + BN - 1) / BN, M / BM, Z);
    gemm_mma<<<grid, 256, SMEM_GEMM, st>>>(A, lda, sA, B, ldb, sB, C, ldc, sC,
                                           Cin, sCin, bias, sBias, lab,
                                           O1, O2, X1, X2, M, N, K, mode, relu);
}

extern "C" void kernel_launch(void* const* d_in, const int* in_sizes, int n_in,
                              void* d_out, int out_size)
{
    const float* inputs = (const float*)d_in[0];
    const int*   labels = (const int*)  d_in[1];
    const float* start  = (const float*)d_in[2];
    const float* emb    = (const float*)d_in[3];
    const float* W_ih0  = (const float*)d_in[4];
    const float* W_hh0  = (const float*)d_in[5];
    const float* b_ih0  = (const float*)d_in[6];
    const float* b_hh0  = (const float*)d_in[7];
    const float* hwN_W0 = (const float*)d_in[8];
    const float* hwN_b0 = (const float*)d_in[9];
    const float* hwL_W0 = (const float*)d_in[10];
    const float* W_ih1  = (const float*)d_in[11];
    const float* W_hh1  = (const float*)d_in[12];
    const float* b_ih1  = (const float*)d_in[13];
    const float* b_hh1  = (const float*)d_in[14];
    // d_in[15..17] dead in reference (layer-1 highway output unused)
    const float* sh_W   = (const float*)d_in[18];
    const float* sh_b   = (const float*)d_in[19];
    const float* pred_W = (const float*)d_in[20];
    const float* pred_b = (const float*)d_in[21];
    float* out = (float*)d_out;

    static cudaStream_t sPre = nullptr, sCls = nullptr;
    static cudaEvent_t evSetup, evPa[S_], evPb[S_], evM[S_], evLast;
    if (!sPre) {
        int lo, hi;
        cudaDeviceGetStreamPriorityRange(&lo, &hi);   // lo = lowest priority
        cudaStreamCreateWithPriority(&sPre, cudaStreamNonBlocking, lo);
        cudaStreamCreateWithPriority(&sCls, cudaStreamNonBlocking, lo);
        cudaEventCreateWithFlags(&evSetup, cudaEventDisableTiming);
        cudaEventCreateWithFlags(&evLast, cudaEventDisableTiming);
        for (int i = 0; i < S_; ++i) {
            cudaEventCreateWithFlags(&evPa[i], cudaEventDisableTiming);
            cudaEventCreateWithFlags(&evPb[i], cudaEventDisableTiming);
            cudaEventCreateWithFlags(&evM[i], cudaEventDisableTiming);
        }
        cudaFuncSetAttribute(gemm_mma, cudaFuncAttributeMaxDynamicSharedMemorySize,
                             SMEM_GEMM);
    }

    float *P_ih0, *P_NL, *We, *biasAll, *bias1, *h0f, *c0, *c1;
    half_t *embA, *WembA, *INP, *WihD, *WNLD, *Whh0i, *WhhN, *Wcat1, *SHW, *PW;
    half_t *h0A, *cat1, *h1p, *hid;
    int *labAll;
    SYM(P_ih0, g_P_ih0); SYM(P_NL, g_P_NL); SYM(We, g_We);
    SYM(biasAll, g_biasAll); SYM(bias1, g_bias1);
    SYM(h0f, g_h0f); SYM(c0, g_c0); SYM(c1, g_c1);
    SYM(embA, g_embA); SYM(WembA, g_WembA); SYM(INP, g_INP);
    SYM(WihD, g_WihD); SYM(WNLD, g_WNLD);
    SYM(Whh0i, g_Whh0i); SYM(WhhN, g_WhhN); SYM(Wcat1, g_Wcat1);
    SYM(SHW, g_SHW); SYM(PW, g_PW);
    SYM(h0A, g_h0A); SYM(cat1, g_cat1); SYM(h1p, g_h1p); SYM(hid, g_hid);
    SYM(labAll, g_labAll);

    const long h0sz = (long)BATCH * H_;
    const long c1sz = (long)BATCH * 1024;
    const int CB = 2048;
    const long BIGR = 1L << 40;

    // ---- init ----
    cudaMemsetAsync(c0, 0, h0sz * 4);
    cudaMemsetAsync(c1, 0, h0sz * 4);
    cudaMemsetAsync(h0A, 0, h0sz * 2);    // slot-0 h0
    cudaMemsetAsync(cat1, 0, c1sz * 2);   // slot-0 [cur|h1]

    // ---- pack weights (stream 0) ----
    // WihD: W_ih0[:, :D] gate-interleaved (dst 2048 rows/slot, ld 1024)
    conv_pack<<<CB, 256>>>(W_ih0, D0_, 0, 0, 0, WihD, D_, 0, H4_, 0,
                           0, -1, H_, (long)S_ * H4_, D_, BIGR);
    // WembA rows 0-2047: W_ih0[:, D:] gate-interleaved (dst 3072 rows/slot, ld 256)
    conv_pack<<<CB, 256>>>(W_ih0, D0_, D_, 0, 0, WembA, E_, 0, NW, 0,
                           0, -1, H_, (long)S_ * H4_, E_, BIGR);
    // Whh0i: W_hh0 gate-interleaved
    conv_pack<<<CB, 256>>>(W_hh0, H_, 0, 0, 0, Whh0i, H_, 0, H4_, 0,
                           0, -1, H_, (long)S_ * H4_, H_, BIGR);
    // Wcat1: [W_ih1 | W_hh1] gate-interleaved
    conv_pack<<<CB, 256>>>(W_ih1, H_, 0, 0, 0, Wcat1, 1024, 0, H4_, 0,
                           0, -1, H_, (long)S_ * H4_, H_, BIGR);
    conv_pack<<<CB, 256>>>(W_hh1, H_, 0, 0, 0, Wcat1, 1024, 512, H4_, 0,
                           0, -1, H_, (long)S_ * H4_, H_, BIGR);
    // WNLD: stacked hwN[:, :D] / hwL[:, :D]
    conv_pack<<<CB, 256>>>(hwN_W0, D0_ + H_, 0, H_, 0, WNLD, D_, 0, 1024, 0,
                           0, -1, 0, (long)S_ * H_, D_, H_);
    conv_pack<<<CB, 256>>>(hwL_W0, D0_, 0, H_, 0, WNLD, D_, 0, 1024, 512,
                           0, -1, 0, (long)S_ * H_, D_, H_);
    // WembA rows 2048-2559: hwN[:, D:D0]; rows 2560-3071: hwL[:, D:D0]
    conv_pack<<<CB, 256>>>(hwN_W0, D0_ + H_, D_, H_, 0, WembA, E_, 0, NW, 2048,
                           0, -1, 0, (long)S_ * H_, E_, H_);
    conv_pack<<<CB, 256>>>(hwL_W0, D0_, D_, H_, 0, WembA, E_, 0, NW, 2560,
                           0, -1, 0, (long)S_ * H_, E_, H_);
    // WhhN: hwN[:, D0:]
    conv_pack<<<CB, 256>>>(hwN_W0, D0_ + H_, D0_, 0, 0, WhhN, H_, 0, 0, 0,
                           0, -1, 0, (long)S_ * H_, H_, BIGR);
    // classifier weights (A-split duplicated)
    conv_pack<<<CB, 256>>>(sh_W, H_, 0, 0, 0, SHW, H1K, 0, 0, 0, 512, 0, 0,
                           (long)S_ * SH_, H_, BIGR);
    conv_pack<<<CB, 256>>>(pred_W, SH_, 0, 0, 0, PW, HIDK, 0, 0, 0, 256, 0, 0,
                           (long)S_ * V_, SH_, BIGR);
    // inputs fp16
    conv_pack<<<CB, 256>>>(inputs, D_, 0, 0, 0, INP, D_, 0, 0, 0, 0, -1, 0,
                           (long)BATCH, D_, BIGR);
    emba_build<<<CB, 256>>>(start, emb);
    misc_init<<<CB, 256>>>(b_ih0, b_hh0, b_ih1, b_hh1, hwN_b0, labels);
    cudaEventRecord(evSetup, 0);

    // ---- sPre: vocab GEMM + per-slot precompute (overlaps serial chain) ----
    cudaStreamWaitEvent(sPre, evSetup, 0);
    // We[s] = embA[s] @ WembA[s].T + biasAll[s]   (M=128, N=3072, K=256, z=S)
    G(embA, E_, 128L * E_, WembA, E_, (long)NW * E_,
      We, NW, 128L * NW, nullptr, 0, biasAll, NW, nullptr,
      nullptr, nullptr, nullptr, nullptr, 128, NW, E_, 0, 0, S_, sPre);
    for (int s = 0; s < S_; ++s) {
        // P_ih0[s] = INP @ WihD[s].T + We[s][lab]   (gather epilogue)
        G(INP, D_, 0,
          WihD + (long)s * H4_ * D_, D_, 0,
          P_ih0 + (long)s * BATCH * H4_, H4_, 0,
          We + (long)s * 128 * NW, 0, nullptr, 0, labAll + (long)s * BATCH,
          nullptr, nullptr, nullptr, nullptr, BATCH, H4_, D_, 0, 0, 1, sPre);
        cudaEventRecord(evPa[s], sPre);
        // P_NL[s] = INP @ WNLD[s].T + We[s][lab][2048:]
        G(INP, D_, 0,
          WNLD + (long)s * 1024 * D_, D_, 0,
          P_NL + (long)s * BATCH * 1024, 1024, 0,
          We + (long)s * 128 * NW + 2048, 0, nullptr, 0, labAll + (long)s * BATCH,
          nullptr, nullptr, nullptr, nullptr, BATCH, 1024, D_, 0, 0, 1, sPre);
        cudaEventRecord(evPb[s], sPre);
    }

    // ---- serial chain on main stream ----
    for (int s = 0; s < S_; ++s) {
        cudaStreamWaitEvent(0, evPa[s], 0);
        // gates0 + LSTM0: h0(s-1) @ W_hh0 + P_ih0[s]  -> h0(s)
        G(h0A + (long)s * h0sz, H_, 0,
          Whh0i + (long)s * H4_ * H_, H_, 0,
          nullptr, H4_, 0, P_ih0 + (long)s * BATCH * H4_, 0, nullptr, 0, nullptr,
          h0A + (long)(s + 1) * h0sz, nullptr, c0, h0f,
          BATCH, H4_, H_, 2, 0, 1, 0);

        cudaStreamWaitEvent(0, evPb[s], 0);
        // gateN + highway (frag-direct): h0(s) @ hwN_h + P_NL[s] -> cur into cat1[s]
        G(h0A + (long)(s + 1) * h0sz, H_, 0,
          WhhN + (long)s * H_ * H_, H_, 0,
          nullptr, 1024, 0, P_NL + (long)s * BATCH * 1024, 0, nullptr, 0, nullptr,
          cat1 + (long)s * c1sz, nullptr, h0f, nullptr,
          BATCH, H_, H_, 3, 0, 1, 0);

        // gates1 + LSTM1: [cur|h1(s-1)] @ Wcat1 + bias1 -> h1(s)
        G(cat1 + (long)s * c1sz, 1024, 0,
          Wcat1 + (long)s * H4_ * 1024, 1024, 0,
          nullptr, H4_, 0, nullptr, 0, bias1 + (long)s * H4_, 0, nullptr,
          cat1 + (long)(s + 1) * c1sz, h1p + (long)s * BATCH * H1K, c1, nullptr,
          BATCH, H4_, 1024, 4, 0, 1, 0);

        cudaEventRecord(evM[s], 0);
    }

    // ---- classifier chain on second low-priority stream ----
    for (int s = 0; s < S_; ++s) {
        cudaStreamWaitEvent(sCls, evM[s], 0);
        G(h1p + (long)s * BATCH * H1K, H1K, 0,
          SHW + (long)s * SH_ * H1K, H1K, 0,
          nullptr, HIDK, 0, nullptr, 0, sh_b + (long)s * SH_, 0, nullptr,
          hid + (long)s * BATCH * HIDK, nullptr, nullptr, nullptr,
          BATCH, SH_, H1K, 1, 1, 1, sCls);
        G(hid + (long)s * BATCH * HIDK, HIDK, 0,
          PW + (long)s * V_ * HIDK, HIDK, 0,
          out + (long)s * BATCH * V_, V_, 0, nullptr, 0, pred_b + (long)s * V_, 0,
          nullptr, nullptr, nullptr, nullptr, nullptr,
          BATCH, V_, HIDK, 0, 0, 1, sCls);
    }
    cudaEventRecord(evLast, sCls);
    cudaStreamWaitEvent(0, evLast, 0);
}